// round 6
// baseline (speedup 1.0000x reference)
#include <cuda_runtime.h>
#include <cstdint>

// CTC forward loss, B=32, T=2048, V=1024, S=256. Single kernel.
// One CTA per batch, 256 threads. Thread i owns positions 2i+1 (token, aT)
// and 2i+2 (blank, aB); thread 0 also position 0 (a0, pure add).
// FUSED 2-STEP loop: each iteration advances two time steps with ONE
// barrier. Step A computes own positions plus redundant left-neighbor
// positions (s-1, s-2) from shfl_up distance 1/2; step B is then fully
// local. Warp boundaries pass 4 values (lanes 30,31) through smem,
// parity double-buffered. Log-prob rows streamed via 11-stage cp.async.
// Loss reduction folded in via last-block pattern (deterministic order).

#define TT 2048
#define VV 1024
#define SS 256
#define BB 32
#define NEGF (-1e30f)
#define STAGES 11
#define NTHREADS 256
#define NWARPS 8

__device__ float g_losses[BB];
__device__ unsigned int g_done;   // zero-initialized; self-resetting

__device__ __forceinline__ void cp_async16(uint32_t smem_addr, const void* gmem) {
    asm volatile("cp.async.cg.shared.global [%0], [%1], 16;\n"
                 :: "r"(smem_addr), "l"(gmem));
}
__device__ __forceinline__ void cp_commit() {
    asm volatile("cp.async.commit_group;\n" ::: "memory");
}
template <int N>
__device__ __forceinline__ void cp_wait() {
    asm volatile("cp.async.wait_group %0;\n" :: "n"(N) : "memory");
}

// LSE2: m + log(1 + e^(lo-m))  (max term's exp == 1)
__device__ __forceinline__ float lse2(float a, float b) {
    const float m  = fmaxf(a, b);
    const float lo = fminf(a, b);
    return m + __logf(1.0f + __expf(lo - m));
}
// LSE3 with max term's exp folded into the constant 1.
__device__ __forceinline__ float lse3(float x0, float x1, float x2) {
    const float lo1 = fminf(x0, x1);
    const float hi1 = fmaxf(x0, x1);
    const float m   = fmaxf(hi1, x2);
    const float o2  = fminf(hi1, x2);
    return m + __logf(1.0f + __expf(lo1 - m) + __expf(o2 - m));
}

__global__ void __launch_bounds__(NTHREADS, 1)
ctc_fused(const float* __restrict__ lp,     // [B, T, V] log-probs
          const int* __restrict__ tok,      // [B, S]
          const int* __restrict__ tlens,    // [B]
          const int* __restrict__ slens,    // [B]
          float* __restrict__ out) {
    __shared__ float rows[STAGES][VV];      // 44 KB streamed log-prob rows
    __shared__ float bnd[2][NWARPS][4];     // {aT30,aB30,aT31,aB31} per warp

    const int b    = blockIdx.x;
    const int tid  = threadIdx.x;
    const int lane = tid & 31;
    const int w    = tid >> 5;
    const int Tl   = tlens[b];
    const int Sl   = slens[b];
    const float* lpb = lp + (size_t)b * TT * VV;

    // Own token (pos 2i+1) and left-neighbor token (pos 2i-1) labels/flags.
    const int  Li   = tok[b * SS + tid];
    const int  Lp   = (tid >= 1) ? tok[b * SS + tid - 1] : 0;
    const int  Lq   = (tid >= 2) ? tok[b * SS + tid - 2] : 0;
    const bool repi = (tid >= 1) && (Li != Lp);
    const bool repp = (tid >= 2) && (Lp != Lq);

    // Prologue: rows 0..10 in groups {0,1}{2,3}{4,5}{6,7}{8,9}{10}.
    #pragma unroll
    for (int st = 0; st < STAGES; ++st) {
        cp_async16((uint32_t)__cvta_generic_to_shared(&rows[st][tid * 4]),
                   lpb + (size_t)st * VV + tid * 4);
        if ((st & 1) || st == STAGES - 1) cp_commit();
    }
    cp_wait<3>();           // rows 0..5 resident
    __syncthreads();

    // t = 0 init.
    float aT = (tid == 0) ? rows[0][Li] : NEGF;
    float aB = NEGF;
    float a0 = rows[0][0];                   // alpha[0], thread 0 only

    // Emit registers for rows 1 (step A) and 2 (step B).
    float eB0 = rows[1][0], eT0 = rows[1][Li], eTp0 = rows[1][Lp];
    float eB1 = rows[2][0], eT1 = rows[2][Li];

    if (lane >= 30) {                        // publish t=0 boundary (buf 1)
        bnd[1][w][(lane - 30) * 2 + 0] = aT;
        bnd[1][w][(lane - 30) * 2 + 1] = aB;
    }
    __syncthreads();

    const int nf = (Tl - 1) >> 1;            // fused iterations
    int sA = 3, sB = 4;                      // slots of rows 2f+3, 2f+4
    int rW = STAGES;                         // next row to stream (11+2f)
    int sW = 0;                              // its slot ((11+2f) % 11)

    for (int f = 0; f < nf; ++f) {
        const int rI = (f + 1) & 1;          // boundary read buffer
        const int wI = f & 1;                // boundary write buffer

        float aT1 = __shfl_up_sync(0xffffffffu, aT, 1);
        float aB1 = __shfl_up_sync(0xffffffffu, aB, 1);
        float aT2 = __shfl_up_sync(0xffffffffu, aT, 2);
        float aB2 = __shfl_up_sync(0xffffffffu, aB, 2);
        float a0b = __shfl_sync(0xffffffffu, a0, 0);
        if (lane == 0) {
            if (w) { aT1 = bnd[rI][w-1][2]; aB1 = bnd[rI][w-1][3];
                     aT2 = bnd[rI][w-1][0]; aB2 = bnd[rI][w-1][1]; }
            else   { aT1 = NEGF; aB1 = a0; aT2 = NEGF; aB2 = NEGF; }
        } else if (lane == 1) {
            if (w) { aT2 = bnd[rI][w-1][2]; aB2 = bnd[rI][w-1][3]; }
            else   { aT2 = NEGF; aB2 = a0b; }
        }

        // ---- Step A (time t = 2f+1): own + redundant left positions ----
        float AoT = eT0  + lse3(aT,  aB1, repi ? aT1 : NEGF);  // pos 2i+1
        float AoB = eB0  + lse2(aB,  aT);                      // pos 2i+2
        float ArT = eTp0 + lse3(aT1, aB2, repp ? aT2 : NEGF);  // pos 2i-1
        float ArB = eB0  + lse2(aB1, aT1);                     // pos 2i
        if (tid == 0) { ArT = NEGF; ArB = eB0 + a0; a0 = ArB; }

        // ---- Step B (time t = 2f+2): fully local ----
        aT = eT1 + lse3(AoT, ArB, repi ? ArT : NEGF);
        aB = eB1 + lse2(AoB, AoT);
        if (tid == 0) a0 = eB1 + a0;

        if (lane >= 30) {
            bnd[wI][w][(lane - 30) * 2 + 0] = aT;
            bnd[wI][w][(lane - 30) * 2 + 1] = aB;
        }

        // Emit regs for next iteration (rows 2f+3, 2f+4; resident).
        eB0 = rows[sA][0]; eT0 = rows[sA][Li]; eTp0 = rows[sA][Lp];
        eB1 = rows[sB][0]; eT1 = rows[sB][Li];
        sA += 2; if (sA >= STAGES) sA -= STAGES;
        sB += 2; if (sB >= STAGES) sB -= STAGES;

        // Stream rows 11+2f, 12+2f (skip past-end rows; commit always).
        if (rW < TT)
            cp_async16((uint32_t)__cvta_generic_to_shared(&rows[sW][tid * 4]),
                       lpb + (size_t)rW * VV + tid * 4);
        {
            int s2 = sW + 1; if (s2 >= STAGES) s2 -= STAGES;
            if (rW + 1 < TT)
                cp_async16((uint32_t)__cvta_generic_to_shared(&rows[s2][tid * 4]),
                           lpb + (size_t)(rW + 1) * VV + tid * 4);
        }
        cp_commit();
        rW += 2; sW += 2; if (sW >= STAGES) sW -= STAGES;
        cp_wait<3>();
        __syncthreads();
    }

    // Remainder single step when (Tl-1) is odd: t = Tl-1 = 2*nf+1.
    // Emit regs already hold row 2*nf+1.
    if ((Tl - 1) & 1) {
        const int rI = (nf + 1) & 1;
        float pT = __shfl_up_sync(0xffffffffu, aT, 1);
        float pB = __shfl_up_sync(0xffffffffu, aB, 1);
        if (lane == 0) {
            if (w) { pT = bnd[rI][w-1][2]; pB = bnd[rI][w-1][3]; }
            else   { pT = NEGF; pB = a0; }
        }
        const float nT = eT0 + lse3(aT, pB, repi ? pT : NEGF);
        const float nB = eB0 + lse2(aB, aT);
        aT = nT; aB = nB;
    }

    // Loss: thread Sl-1 holds alpha[2Sl-1]=aT, alpha[2Sl]=aB.
    if (tid == Sl - 1) {
        float loss = -lse2(aB, aT);
        if (loss > 1e29f) loss = 0.0f;
        g_losses[b] = loss / (float)Sl;
        __threadfence();
    }
    __syncthreads();

    // Last-block deterministic reduction (fixed order, self-resetting flag).
    if (tid == 0) {
        __threadfence();
        const unsigned v = atomicAdd(&g_done, 1u);
        if (v == BB - 1) {
            __threadfence();
            float acc = 0.0f;
            #pragma unroll
            for (int i = 0; i < BB; ++i) acc += g_losses[i];
            out[0] = acc / (float)BB;
            atomicExch(&g_done, 0u);
        }
    }
}

extern "C" void kernel_launch(void* const* d_in, const int* in_sizes, int n_in,
                              void* d_out, int out_size) {
    const float* lp    = (const float*)d_in[0];  // [B,T,V] f32
    const int*   tok   = (const int*)d_in[1];    // [B,S]   i32
    const int*   tlens = (const int*)d_in[2];    // [B]     i32
    const int*   slens = (const int*)d_in[3];    // [B]     i32
    float* out = (float*)d_out;

    ctc_fused<<<BB, NTHREADS>>>(lp, tok, tlens, slens, out);
}